// round 16
// baseline (speedup 1.0000x reference)
#include <cuda_runtime.h>
#include <cuda_fp16.h>
#include <math.h>
#include <stdint.h>

#define NJ 24
#define NV 20000
#define NG 2
#define HID 128
#define EPSV 1e-8f
#define TPB 256
#define MTILE 256   // points per CTA (2 x 128 sub-tiles sharing staged weights)

// main smem: wf[4096] uint4 (64KB: layer1 0..2047, layer2 2048..4095) | f32 tail
#define OFF_F32 65536
#define SMEM_MAIN (65536 + (896 + 4 * 128) * 4)
#define SMEM_SETUP 65536

__device__ float g_c[NJ][4];
__device__ float g_geom[NJ][NG][16];
__device__ float g_pred[NJ][NV];
// fragment-major fp16 weights, nt-paired: [layer][j][(kk*8+ntp)*32+lane] =
//   {b(nt=2ntp).x, b(nt=2ntp).y, b(nt=2ntp+1).x, b(nt=2ntp+1).y}
__device__ uint4 g_Wf4[2][NJ][2048];

__device__ __forceinline__ float sp100(float x) {
    float t = 100.0f * x;
    if (t > 20.0f) return x;
    return log1pf(expf(t)) * 0.01f;
}
__device__ __forceinline__ float sp100f(float x) {
    return fmaxf(x, 0.0f) + __logf(1.0f + __expf(-fabsf(100.0f * x))) * 0.01f;
}
__device__ __forceinline__ float ra_elu(float x) {
    return (x - 1.0f) > 0.0f ? x : expf(x - 1.0f);
}
__device__ __forceinline__ uint32_t f2h2(float a, float b) {
    __half2 h = __floats2half2_rn(a, b);
    return *reinterpret_cast<uint32_t*>(&h);
}
__device__ __forceinline__ void mma_f16(float* c, const uint32_t* a, uint32_t b0, uint32_t b1) {
    asm volatile(
        "mma.sync.aligned.m16n8k16.row.col.f32.f16.f16.f32 "
        "{%0,%1,%2,%3}, {%4,%5,%6,%7}, {%8,%9}, {%0,%1,%2,%3};"
        : "+f"(c[0]), "+f"(c[1]), "+f"(c[2]), "+f"(c[3])
        : "r"(a[0]), "r"(a[1]), "r"(a[2]), "r"(a[3]), "r"(b0), "r"(b1));
}

// ---------------------------------------------------------------------------
// Setup kernel: blocks 0..47 = weight conversion (j = b>>1, layer = b&1),
// blocks 48..71 = per-part precompute, one part per block, block-parallel GEMV
// ---------------------------------------------------------------------------
__global__ __launch_bounds__(256, 1) void setup_kernel(
    const float* __restrict__ W1, const float* __restrict__ W2,
    const float* __restrict__ Bcond, const float* __restrict__ Bneigh,
    const float* __restrict__ alpha, const float* __restrict__ beta,
    const float* __restrict__ cW0, const float* __restrict__ cb0,
    const float* __restrict__ cW1, const float* __restrict__ cb1,
    const float* __restrict__ cW2, const float* __restrict__ cb2)
{
    extern __shared__ float Wsm[];   // 16384 floats (64KB) for wconv blocks
    int tid = threadIdx.x;
    int b = blockIdx.x;

    if (b < 2 * NJ) {
        // ---- weight conversion ----
        int j = b >> 1, layer = b & 1;
        const float* W = (layer == 0 ? W1 : W2) + (size_t)j * HID * HID;
        const float4* src = (const float4*)W;
        float4* dst = (float4*)Wsm;
        #pragma unroll
        for (int i = 0; i < 16; i++) dst[tid + i * 256] = src[tid + i * 256];
        __syncthreads();
        #pragma unroll
        for (int i = 0; i < 8; i++) {
            int idx4 = tid + i * 256;
            int lane = idx4 & 31;
            int ntp  = (idx4 >> 5) & 7;
            int kk   = idx4 >> 8;
            int ne = ntp * 16 + (lane >> 2);
            int no = ne + 8;
            int c  = kk * 16 + (lane & 3) * 2;
            uint4 bb;
            bb.x = f2h2(Wsm[c * HID + ne], Wsm[(c + 1) * HID + ne]);
            bb.y = f2h2(Wsm[(c + 8) * HID + ne], Wsm[(c + 9) * HID + ne]);
            bb.z = f2h2(Wsm[c * HID + no], Wsm[(c + 1) * HID + no]);
            bb.w = f2h2(Wsm[(c + 8) * HID + no], Wsm[(c + 9) * HID + no]);
            g_Wf4[layer][j][idx4] = bb;
        }
        return;
    }

    // ---- per-part precompute: one j per block, 256-thread GEMV ----
    int j = b - 2 * NJ;
    float* partial = Wsm;            // [16][16] partial sums
    float* c0s = Wsm + 256;          // [16]
    float* c1s = Wsm + 272;          // [16]

    {
        // cond layer0: 288 -> 16; thread = output o (16) x k-segment (16 x 18)
        int o = tid & 15, seg = tid >> 4;
        const float* wp = cW0 + (size_t)j * 288 * 16 + o;
        const float* cond = Bcond + j * 288;
        float s = 0.f;
        int k0 = seg * 18;
        #pragma unroll
        for (int k = 0; k < 18; k++) s += cond[k0 + k] * wp[(k0 + k) * 16];
        partial[seg * 16 + o] = s;
    }
    __syncthreads();
    if (tid < 16) {
        float s = cb0[j * 16 + tid];
        #pragma unroll
        for (int seg = 0; seg < 16; seg++) s += partial[seg * 16 + tid];
        c0s[tid] = sp100(s);
    }
    __syncthreads();
    if (tid < 16) {
        float t = cb1[j * 16 + tid];
        #pragma unroll
        for (int k = 0; k < 16; k++) t += c0s[k] * cW1[j * 256 + k * 16 + tid];
        c1s[tid] = sp100(t);
    }
    __syncthreads();
    if (tid < 4) {
        float u = cb2[j * 4 + tid];
        #pragma unroll
        for (int k = 0; k < 16; k++) u += c1s[k] * cW2[j * 64 + k * 4 + tid];
        g_c[j][tid] = u;
    }

    if (tid < NG) {
        int gi = tid;
        const float* bn = Bneigh + ((j * NG + gi) * 5) * 3;
        float Jt[3] = { bn[0], bn[1], bn[2] };
        float Jc[3] = { bn[3], bn[4], bn[5] };
        float Jo[3] = { bn[6], bn[7], bn[8] };
        float Jp[3] = { bn[9], bn[10], bn[11] };
        int bt = (int)bn[12], bo = (int)bn[13];
        float a_n = ra_elu(alpha[bo * NJ + bt]);
        float a_s = ra_elu(alpha[bt * NJ + bo]);
        float be_n = beta[bo * NJ + bt];
        float be_s = beta[bt * NJ + bo];
        float nb_n = 0.f, nb_s = 0.f;
        for (int d = 0; d < 3; d++) {
            float tn = Jo[d] - Jc[d]; nb_n += tn * tn;
            float ts = Jt[d] - Jc[d]; nb_s += ts * ts;
        }
        nb_n = sqrtf(nb_n); nb_s = sqrtf(nb_s);
        float vn[3], vs[3];
        float f1 = nb_n / (nb_n + nb_s + EPSV);
        for (int d = 0; d < 3; d++) vn[d] = (Jo[d] - Jt[d]) * f1;
        float f2 = nb_s / (nb_n + EPSV);
        for (int d = 0; d < 3; d++) vs[d] = -vn[d] * f2;
        float n_n = 0.f, n_s = 0.f;
        for (int d = 0; d < 3; d++) { n_n += vn[d] * vn[d]; n_s += vs[d] * vs[d]; }
        n_n = sqrtf(n_n); n_s = sqrtf(n_s);
        float cn = a_n / ((n_n + EPSV) * (n_n + EPSV));
        float cs = a_s / ((n_s + EPSV) * (n_s + EPSV));
        float* gg = g_geom[j][gi];
        for (int d = 0; d < 3; d++) gg[d] = Jo[d] - vn[d];
        for (int d = 0; d < 3; d++) gg[3 + d] = vn[d] * cn - vs[d] * cs;
        gg[6] = be_n - be_s;
        for (int d = 0; d < 3; d++) gg[7 + d] = Jp[d];
        for (int d = 0; d < 3; d++) gg[10 + d] = Jc[d];
    }
}

// ---------------------------------------------------------------------------
// Main kernel: 256 points x 1 part per CTA (2 sub-tiles reuse staged weights),
// single-pass fp16 mma, register-resident activations, 2 CTAs/SM
// ---------------------------------------------------------------------------
__global__ __launch_bounds__(TPB, 2) void main_kernel(
    const float* __restrict__ pts, const float* __restrict__ Btr, const float* __restrict__ Brot,
    const float* __restrict__ W0, const float* __restrict__ b0,
    const float* __restrict__ b1, const float* __restrict__ b2,
    const float* __restrict__ W3, const float* __restrict__ b3)
{
    extern __shared__ char sm[];
    uint4* wf = (uint4*)sm;                 // [0..2047]=layer1, [2048..4095]=layer2
    float* w0s = (float*)(sm + OFF_F32);
    float* b0s = w0s + 896;
    float* b1s = b0s + 128;
    float* b2s = b1s + 128;
    float* w3s = b2s + 128;

    int tid = threadIdx.x;
    int j = blockIdx.y;
    int w = tid >> 5, lane = tid & 31;
    int g = lane >> 2, tig = lane & 3;

    // ---- stage both layers' fragments + w0 + biases (once per CTA) ----
    {
        const uint4* s1 = &g_Wf4[0][j][0];
        const uint4* s2 = &g_Wf4[1][j][0];
        #pragma unroll
        for (int i = 0; i < 8; i++) {
            wf[tid + i * TPB] = s1[tid + i * TPB];
            wf[2048 + tid + i * TPB] = s2[tid + i * TPB];
        }
        for (int i = tid; i < 896; i += TPB) w0s[i] = W0[j * 896 + i];
        if (tid < 128) {
            b0s[tid] = b0[j * 128 + tid];
            b1s[tid] = b1[j * 128 + tid];
            b2s[tid] = b2[j * 128 + tid];
            w3s[tid] = W3[j * 128 + tid];
        }
    }
    __syncthreads();   // weights + biases staged (read-only afterwards)

    int grow = lane & 15;

    #pragma unroll 1
    for (int tile = 0; tile < 2; tile++) {
        int v0 = blockIdx.x * MTILE + tile * 128;

        // ---- geometry: lane L computes row (L & 15) of this warp's 16 rows ----
        int v = v0 + w * 16 + grow;
        int vc = v < NV ? v : NV - 1;
        float xk[7];
        {
            float px = pts[vc * 3 + 0] - Btr[j * 3 + 0];
            float py = pts[vc * 3 + 1] - Btr[j * 3 + 1];
            float pz = pts[vc * 3 + 2] - Btr[j * 3 + 2];
            const float* R = Brot + j * 9;
            float plx = R[0] * px + R[3] * py + R[6] * pz;
            float ply = R[1] * px + R[4] * py + R[7] * pz;
            float plz = R[2] * px + R[5] * py + R[8] * pz;
            float ox = 0.f, oy = 0.f, oz = 0.f;
            #pragma unroll
            for (int gi = 0; gi < NG; gi++) {
                const float* gg = g_geom[j][gi];
                float dx = plx - gg[0], dy = ply - gg[1], dz = plz - gg[2];
                float arg = dx * gg[3] + dy * gg[4] + dz * gg[5] + gg[6];
                float ww = 1.0f / (1.0f + expf(-arg));
                float ax = -gg[7] * ww, ay = -gg[8] * ww, az = -gg[9] * ww;
                float ang = sqrtf(ax * ax + ay * ay + az * az);
                float inv = (ang < 1e-12f) ? 1.0f : (1.0f / ang);
                float ux = ax * inv, uy = ay * inv, uz = az * inv;
                float cc = cosf(ang), ss = sinf(ang);
                float C = 1.0f - cc;
                float qx = plx - gg[10], qy = ply - gg[11], qz = plz - gg[12];
                float rx = (cc + ux * ux * C) * qx + (ux * uy * C - uz * ss) * qy + (ux * uz * C + uy * ss) * qz;
                float ry = (uy * ux * C + uz * ss) * qx + (cc + uy * uy * C) * qy + (uy * uz * C - ux * ss) * qz;
                float rz = (uz * ux * C - uy * ss) * qx + (uz * uy * C + ux * ss) * qy + (cc + uz * uz * C) * qz;
                ox += rx + gg[10] - plx;
                oy += ry + gg[11] - ply;
                oz += rz + gg[12] - plz;
            }
            xk[0] = plx + ox; xk[1] = ply + oy; xk[2] = plz + oz;
            xk[3] = g_c[j][0]; xk[4] = g_c[j][1]; xk[5] = g_c[j][2]; xk[6] = g_c[j][3];
        }

        // redistribute xk: this thread owns rows g and g+8
        float xka[7], xkb[7];
        #pragma unroll
        for (int k = 0; k < 7; k++) {
            xka[k] = __shfl_sync(0xffffffffu, xk[k], g);
            xkb[k] = __shfl_sync(0xffffffffu, xk[k], g + 8);
        }

        // ---- layer0 (7 -> 128) directly into A fragments (registers) ----
        uint32_t frag[8][4];
        #pragma unroll
        for (int kk = 0; kk < 8; kk++) {
            int c = kk * 16 + tig * 2;
            int cols[4] = { c, c + 1, c + 8, c + 9 };
            float sa[4], sb[4];
            #pragma unroll
            for (int ci = 0; ci < 4; ci++) { sa[ci] = b0s[cols[ci]]; sb[ci] = sa[ci]; }
            #pragma unroll
            for (int k = 0; k < 7; k++) {
                #pragma unroll
                for (int ci = 0; ci < 4; ci++) {
                    float wv = w0s[k * 128 + cols[ci]];
                    sa[ci] += xka[k] * wv;
                    sb[ci] += xkb[k] * wv;
                }
            }
            frag[kk][0] = f2h2(sp100f(sa[0]), sp100f(sa[1]));
            frag[kk][1] = f2h2(sp100f(sb[0]), sp100f(sb[1]));
            frag[kk][2] = f2h2(sp100f(sa[2]), sp100f(sa[3]));
            frag[kk][3] = f2h2(sp100f(sb[2]), sp100f(sb[3]));
        }

        // ================= layer 1 =================
        float acc[16][4];
        #pragma unroll
        for (int nt = 0; nt < 16; nt++)
            #pragma unroll
            for (int q = 0; q < 4; q++) acc[nt][q] = 0.f;

        #pragma unroll
        for (int kk = 0; kk < 8; kk++) {
            const uint4* wrow = wf + kk * 256 + lane;
            #pragma unroll
            for (int ntp = 0; ntp < 8; ntp++) {
                uint4 bb = wrow[ntp * 32];
                mma_f16(acc[2 * ntp],     frag[kk], bb.x, bb.y);
                mma_f16(acc[2 * ntp + 1], frag[kk], bb.z, bb.w);
            }
        }

        // ---- epilogue layer1: bias + softplus -> layer-2 A fragments ----
        #pragma unroll
        for (int kk = 0; kk < 8; kk++) {
            int n0 = kk * 16 + tig * 2;
            int n1 = n0 + 8;
            frag[kk][0] = f2h2(sp100f(acc[2 * kk][0] + b1s[n0]), sp100f(acc[2 * kk][1] + b1s[n0 + 1]));
            frag[kk][1] = f2h2(sp100f(acc[2 * kk][2] + b1s[n0]), sp100f(acc[2 * kk][3] + b1s[n0 + 1]));
            frag[kk][2] = f2h2(sp100f(acc[2 * kk + 1][0] + b1s[n1]), sp100f(acc[2 * kk + 1][1] + b1s[n1 + 1]));
            frag[kk][3] = f2h2(sp100f(acc[2 * kk + 1][2] + b1s[n1]), sp100f(acc[2 * kk + 1][3] + b1s[n1 + 1]));
        }

        // ================= layer 2 =================
        #pragma unroll
        for (int nt = 0; nt < 16; nt++)
            #pragma unroll
            for (int q = 0; q < 4; q++) acc[nt][q] = 0.f;

        #pragma unroll
        for (int kk = 0; kk < 8; kk++) {
            const uint4* wrow = wf + 2048 + kk * 256 + lane;
            #pragma unroll
            for (int ntp = 0; ntp < 8; ntp++) {
                uint4 bb = wrow[ntp * 32];
                mma_f16(acc[2 * ntp],     frag[kk], bb.x, bb.y);
                mma_f16(acc[2 * ntp + 1], frag[kk], bb.z, bb.w);
            }
        }

        // ---- epilogue layer2 + layer3 dot + quad reduce ----
        {
            float dot0 = 0.f, dot1 = 0.f;
            #pragma unroll
            for (int nt = 0; nt < 16; nt++) {
                int n = nt * 8 + tig * 2;
                dot0 += sp100f(acc[nt][0] + b2s[n]) * w3s[n];
                dot0 += sp100f(acc[nt][1] + b2s[n + 1]) * w3s[n + 1];
                dot1 += sp100f(acc[nt][2] + b2s[n]) * w3s[n];
                dot1 += sp100f(acc[nt][3] + b2s[n + 1]) * w3s[n + 1];
            }
            dot0 += __shfl_xor_sync(0xffffffffu, dot0, 1);
            dot0 += __shfl_xor_sync(0xffffffffu, dot0, 2);
            dot1 += __shfl_xor_sync(0xffffffffu, dot1, 1);
            dot1 += __shfl_xor_sync(0xffffffffu, dot1, 2);
            if (tig == 0) {
                float bb = b3[j];
                int m0 = w * 16 + g;
                int va = v0 + m0;
                int vb = v0 + m0 + 8;
                if (va < NV) g_pred[j][va] = dot0 + bb;
                if (vb < NV) g_pred[j][vb] = dot1 + bb;
            }
        }
    }
}

// ---------------------------------------------------------------------------
// Softmin blend over parts
// ---------------------------------------------------------------------------
__global__ void softmin_kernel(float* __restrict__ out) {
    int v = blockIdx.x * blockDim.x + threadIdx.x;
    if (v >= NV) return;
    float p[NJ];
    float mn = 3.0e38f;
    #pragma unroll
    for (int j = 0; j < NJ; j++) { p[j] = g_pred[j][v]; mn = fminf(mn, p[j]); }
    float se = 0.f, sd = 0.f;
    #pragma unroll
    for (int j = 0; j < NJ; j++) {
        float d = p[j] - mn;
        float e = expf(-200.0f * d);
        se += e;
        sd += d * e;
    }
    out[v] = sd / se + mn;
}

extern "C" void kernel_launch(void* const* d_in, const int* in_sizes, int n_in,
                              void* d_out, int out_size)
{
    const float* pts    = (const float*)d_in[0];
    const float* Bcond  = (const float*)d_in[1];
    const float* Btr    = (const float*)d_in[2];
    const float* Brot   = (const float*)d_in[3];
    const float* Bneigh = (const float*)d_in[4];
    const float* alpha  = (const float*)d_in[5];
    const float* beta   = (const float*)d_in[6];
    const float* cW0 = (const float*)d_in[7];
    const float* cb0 = (const float*)d_in[8];
    const float* cW1 = (const float*)d_in[9];
    const float* cb1 = (const float*)d_in[10];
    const float* cW2 = (const float*)d_in[11];
    const float* cb2 = (const float*)d_in[12];
    const float* W0  = (const float*)d_in[13];
    const float* b0  = (const float*)d_in[14];
    const float* W1  = (const float*)d_in[15];
    const float* b1  = (const float*)d_in[16];
    const float* W2  = (const float*)d_in[17];
    const float* b2  = (const float*)d_in[18];
    const float* W3  = (const float*)d_in[19];
    const float* b3  = (const float*)d_in[20];

    cudaFuncSetAttribute(setup_kernel, cudaFuncAttributeMaxDynamicSharedMemorySize, SMEM_SETUP);
    cudaFuncSetAttribute(main_kernel, cudaFuncAttributeMaxDynamicSharedMemorySize, SMEM_MAIN);

    setup_kernel<<<3 * NJ, 256, SMEM_SETUP>>>(W1, W2, Bcond, Bneigh, alpha, beta,
                                              cW0, cb0, cW1, cb1, cW2, cb2);

    dim3 grid((NV + MTILE - 1) / MTILE, NJ);
    main_kernel<<<grid, TPB, SMEM_MAIN>>>(pts, Btr, Brot, W0, b0, b1, b2, W3, b3);

    softmin_kernel<<<(NV + 255) / 256, 256>>>((float*)d_out);
}

// round 17
// speedup vs baseline: 1.1482x; 1.1482x over previous
#include <cuda_runtime.h>
#include <cuda_fp16.h>
#include <math.h>
#include <stdint.h>

#define NJ 24
#define NV 20000
#define NG 2
#define HID 128
#define EPSV 1e-8f
#define TPB 256
#define MTILE 128

// main smem: wf[4096] uint4 (64KB) | w0f[256] uint4 (4KB) | b1,b2,w3 f32 | xs fp16 (2KB)
#define OFF_W0F 65536
#define OFF_B1  69632
#define OFF_B2  70144
#define OFF_W3  70656
#define OFF_XS  71168
#define SMEM_MAIN (71168 + 2048)
#define SMEM_SETUP 65536

__device__ float g_c[NJ][4];
__device__ float g_geom[NJ][NG][16];
__device__ float g_pred[NJ][NV];
// fragment-major fp16 weights, nt-paired: [layer][j][(kk*8+ntp)*32+lane]
__device__ uint4 g_Wf4[2][NJ][2048];
// layer0 fragments (K=16: k0..6 = W0, k7 = b0, k8..15 = 0): [j][ntp*32+lane]
__device__ uint4 g_W0f[NJ][256];

__device__ __forceinline__ float sp100(float x) {     // exact (setup only)
    float t = 100.0f * x;
    if (t > 20.0f) return x;
    return log1pf(expf(t)) * 0.01f;
}
// softplus(100x)/100 with single MUFU: max(x,0) + u*q(u)*0.01, u=exp(-|100x|),
// q cubic fit of log1p(u)/u on [0,1] (max err ~4e-4 in log1p -> ~4e-6 in output)
__device__ __forceinline__ float sp100p(float x) {
    float u = __expf(-fabsf(100.0f * x));
    float q = 1.0f + u * (-0.48748f + u * (0.25452f - 0.07389f * u));
    return fmaxf(x, 0.0f) + 0.01f * u * q;
}
__device__ __forceinline__ float ra_elu(float x) {
    return (x - 1.0f) > 0.0f ? x : expf(x - 1.0f);
}
__device__ __forceinline__ uint32_t f2h2(float a, float b) {
    __half2 h = __floats2half2_rn(a, b);
    return *reinterpret_cast<uint32_t*>(&h);
}
__device__ __forceinline__ void mma_f16(float* c, const uint32_t* a, uint32_t b0, uint32_t b1) {
    asm volatile(
        "mma.sync.aligned.m16n8k16.row.col.f32.f16.f16.f32 "
        "{%0,%1,%2,%3}, {%4,%5,%6,%7}, {%8,%9}, {%0,%1,%2,%3};"
        : "+f"(c[0]), "+f"(c[1]), "+f"(c[2]), "+f"(c[3])
        : "r"(a[0]), "r"(a[1]), "r"(a[2]), "r"(a[3]), "r"(b0), "r"(b1));
}

// ---------------------------------------------------------------------------
// Setup: blocks 0..47 = W1/W2 fragment conversion, blocks 48..71 = per-part
// precompute (cond MLP + blending constants + W0 fragment pack)
// ---------------------------------------------------------------------------
__global__ __launch_bounds__(256, 1) void setup_kernel(
    const float* __restrict__ W1, const float* __restrict__ W2,
    const float* __restrict__ Bcond, const float* __restrict__ Bneigh,
    const float* __restrict__ alpha, const float* __restrict__ beta,
    const float* __restrict__ cW0, const float* __restrict__ cb0,
    const float* __restrict__ cW1, const float* __restrict__ cb1,
    const float* __restrict__ cW2, const float* __restrict__ cb2,
    const float* __restrict__ W0, const float* __restrict__ b0)
{
    extern __shared__ float Wsm[];
    int tid = threadIdx.x;
    int b = blockIdx.x;

    if (b < 2 * NJ) {
        int j = b >> 1, layer = b & 1;
        const float* W = (layer == 0 ? W1 : W2) + (size_t)j * HID * HID;
        const float4* src = (const float4*)W;
        float4* dst = (float4*)Wsm;
        #pragma unroll
        for (int i = 0; i < 16; i++) dst[tid + i * 256] = src[tid + i * 256];
        __syncthreads();
        #pragma unroll
        for (int i = 0; i < 8; i++) {
            int idx4 = tid + i * 256;
            int lane = idx4 & 31;
            int ntp  = (idx4 >> 5) & 7;
            int kk   = idx4 >> 8;
            int ne = ntp * 16 + (lane >> 2);
            int no = ne + 8;
            int c  = kk * 16 + (lane & 3) * 2;
            uint4 bb;
            bb.x = f2h2(Wsm[c * HID + ne], Wsm[(c + 1) * HID + ne]);
            bb.y = f2h2(Wsm[(c + 8) * HID + ne], Wsm[(c + 9) * HID + ne]);
            bb.z = f2h2(Wsm[c * HID + no], Wsm[(c + 1) * HID + no]);
            bb.w = f2h2(Wsm[(c + 8) * HID + no], Wsm[(c + 9) * HID + no]);
            g_Wf4[layer][j][idx4] = bb;
        }
        return;
    }

    int j = b - 2 * NJ;

    // ---- W0 fragment pack: k=0..6 W0, k=7 bias, k=8..15 zero ----
    {
        int lane = tid & 31;
        int ntp = tid >> 5;
        int ne = ntp * 16 + (lane >> 2);
        int no = ne + 8;
        int c = (lane & 3) * 2;
        float xe0 = W0[j * 896 + c * HID + ne];
        float xe1 = (c + 1 < 7) ? W0[j * 896 + (c + 1) * HID + ne] : b0[j * HID + ne];
        float xo0 = W0[j * 896 + c * HID + no];
        float xo1 = (c + 1 < 7) ? W0[j * 896 + (c + 1) * HID + no] : b0[j * HID + no];
        uint4 bb;
        bb.x = f2h2(xe0, xe1);
        bb.y = 0u;
        bb.z = f2h2(xo0, xo1);
        bb.w = 0u;
        g_W0f[j][tid] = bb;
    }

    // ---- cond MLP (block-parallel GEMV) ----
    float* partial = Wsm;            // [16][16]
    float* c0s = Wsm + 256;          // [16]
    float* c1s = Wsm + 272;          // [16]
    {
        int o = tid & 15, seg = tid >> 4;
        const float* wp = cW0 + (size_t)j * 288 * 16 + o;
        const float* cond = Bcond + j * 288;
        float s = 0.f;
        int k0 = seg * 18;
        #pragma unroll
        for (int k = 0; k < 18; k++) s += cond[k0 + k] * wp[(k0 + k) * 16];
        partial[seg * 16 + o] = s;
    }
    __syncthreads();
    if (tid < 16) {
        float s = cb0[j * 16 + tid];
        #pragma unroll
        for (int seg = 0; seg < 16; seg++) s += partial[seg * 16 + tid];
        c0s[tid] = sp100(s);
    }
    __syncthreads();
    if (tid < 16) {
        float t = cb1[j * 16 + tid];
        #pragma unroll
        for (int k = 0; k < 16; k++) t += c0s[k] * cW1[j * 256 + k * 16 + tid];
        c1s[tid] = sp100(t);
    }
    __syncthreads();
    if (tid < 4) {
        float u = cb2[j * 4 + tid];
        #pragma unroll
        for (int k = 0; k < 16; k++) u += c1s[k] * cW2[j * 64 + k * 4 + tid];
        g_c[j][tid] = u;
    }

    if (tid < NG) {
        int gi = tid;
        const float* bn = Bneigh + ((j * NG + gi) * 5) * 3;
        float Jt[3] = { bn[0], bn[1], bn[2] };
        float Jc[3] = { bn[3], bn[4], bn[5] };
        float Jo[3] = { bn[6], bn[7], bn[8] };
        float Jp[3] = { bn[9], bn[10], bn[11] };
        int bt = (int)bn[12], bo = (int)bn[13];
        float a_n = ra_elu(alpha[bo * NJ + bt]);
        float a_s = ra_elu(alpha[bt * NJ + bo]);
        float be_n = beta[bo * NJ + bt];
        float be_s = beta[bt * NJ + bo];
        float nb_n = 0.f, nb_s = 0.f;
        for (int d = 0; d < 3; d++) {
            float tn = Jo[d] - Jc[d]; nb_n += tn * tn;
            float ts = Jt[d] - Jc[d]; nb_s += ts * ts;
        }
        nb_n = sqrtf(nb_n); nb_s = sqrtf(nb_s);
        float vn[3], vs[3];
        float f1 = nb_n / (nb_n + nb_s + EPSV);
        for (int d = 0; d < 3; d++) vn[d] = (Jo[d] - Jt[d]) * f1;
        float f2 = nb_s / (nb_n + EPSV);
        for (int d = 0; d < 3; d++) vs[d] = -vn[d] * f2;
        float n_n = 0.f, n_s = 0.f;
        for (int d = 0; d < 3; d++) { n_n += vn[d] * vn[d]; n_s += vs[d] * vs[d]; }
        n_n = sqrtf(n_n); n_s = sqrtf(n_s);
        float cn = a_n / ((n_n + EPSV) * (n_n + EPSV));
        float cs = a_s / ((n_s + EPSV) * (n_s + EPSV));
        float* gg = g_geom[j][gi];
        for (int d = 0; d < 3; d++) gg[d] = Jo[d] - vn[d];
        for (int d = 0; d < 3; d++) gg[3 + d] = vn[d] * cn - vs[d] * cs;
        gg[6] = be_n - be_s;
        for (int d = 0; d < 3; d++) gg[7 + d] = Jp[d];
        for (int d = 0; d < 3; d++) gg[10 + d] = Jc[d];
    }
}

// ---------------------------------------------------------------------------
// Main kernel: 128 points x 1 part per CTA, all layers on tensor pipe,
// single-MUFU softplus, register-resident activations, 2 CTAs/SM
// ---------------------------------------------------------------------------
__global__ __launch_bounds__(TPB, 2) void main_kernel(
    const float* __restrict__ pts, const float* __restrict__ Btr, const float* __restrict__ Brot,
    const float* __restrict__ b1, const float* __restrict__ b2,
    const float* __restrict__ W3, const float* __restrict__ b3)
{
    extern __shared__ char sm[];
    uint4* wf  = (uint4*)sm;                 // [0..2047]=layer1, [2048..4095]=layer2
    uint4* w0f = (uint4*)(sm + OFF_W0F);     // 256
    float* b1s = (float*)(sm + OFF_B1);
    float* b2s = (float*)(sm + OFF_B2);
    float* w3s = (float*)(sm + OFF_W3);
    __half* xs = (__half*)(sm + OFF_XS);     // [128 rows][8 halves]

    int tid = threadIdx.x;
    int j = blockIdx.y;
    int v0 = blockIdx.x * MTILE;
    int w = tid >> 5, lane = tid & 31;
    int g = lane >> 2, tig = lane & 3;

    // ---- stage weights + biases ----
    {
        const uint4* s1 = &g_Wf4[0][j][0];
        const uint4* s2 = &g_Wf4[1][j][0];
        #pragma unroll
        for (int i = 0; i < 8; i++) {
            wf[tid + i * TPB] = s1[tid + i * TPB];
            wf[2048 + tid + i * TPB] = s2[tid + i * TPB];
        }
        w0f[tid] = g_W0f[j][tid];
        if (tid < 128) {
            b1s[tid] = b1[j * 128 + tid];
            b2s[tid] = b2[j * 128 + tid];
            w3s[tid] = W3[j * 128 + tid];
        }
    }

    // ---- geometry: lane L computes row (L & 15) of this warp's 16 rows ----
    int grow = lane & 15;
    int v = v0 + w * 16 + grow;
    int vc = v < NV ? v : NV - 1;
    {
        float px = pts[vc * 3 + 0] - Btr[j * 3 + 0];
        float py = pts[vc * 3 + 1] - Btr[j * 3 + 1];
        float pz = pts[vc * 3 + 2] - Btr[j * 3 + 2];
        const float* R = Brot + j * 9;
        float plx = R[0] * px + R[3] * py + R[6] * pz;
        float ply = R[1] * px + R[4] * py + R[7] * pz;
        float plz = R[2] * px + R[5] * py + R[8] * pz;
        float ox = 0.f, oy = 0.f, oz = 0.f;
        #pragma unroll
        for (int gi = 0; gi < NG; gi++) {
            const float* gg = g_geom[j][gi];
            float dx = plx - gg[0], dy = ply - gg[1], dz = plz - gg[2];
            float arg = dx * gg[3] + dy * gg[4] + dz * gg[5] + gg[6];
            float ww = 1.0f / (1.0f + expf(-arg));
            float ax = -gg[7] * ww, ay = -gg[8] * ww, az = -gg[9] * ww;
            float ang = sqrtf(ax * ax + ay * ay + az * az);
            float inv = (ang < 1e-12f) ? 1.0f : (1.0f / ang);
            float ux = ax * inv, uy = ay * inv, uz = az * inv;
            float cc = cosf(ang), ss = sinf(ang);
            float C = 1.0f - cc;
            float qx = plx - gg[10], qy = ply - gg[11], qz = plz - gg[12];
            float rx = (cc + ux * ux * C) * qx + (ux * uy * C - uz * ss) * qy + (ux * uz * C + uy * ss) * qz;
            float ry = (uy * ux * C + uz * ss) * qx + (cc + uy * uy * C) * qy + (uy * uz * C - ux * ss) * qz;
            float rz = (uz * ux * C - uy * ss) * qx + (uz * uy * C + ux * ss) * qy + (cc + uz * uz * C) * qz;
            ox += rx + gg[10] - plx;
            oy += ry + gg[11] - ply;
            oz += rz + gg[12] - plz;
        }
        if (lane < 16) {
            uint4 xr;
            xr.x = f2h2(plx + ox, ply + oy);
            xr.y = f2h2(plz + oz, g_c[j][0]);
            xr.z = f2h2(g_c[j][1], g_c[j][2]);
            xr.w = f2h2(g_c[j][3], 1.0f);     // constant-1 slot carries the bias
            *(uint4*)(xs + (w * 16 + grow) * 8) = xr;
        }
    }
    __syncwarp();
    __syncthreads();   // weights staged (also covers xs, harmless)

    // ---- A fragments for layer0 (K=16, upper half zero) ----
    uint32_t a0l[4];
    a0l[0] = *(const uint32_t*)(xs + (w * 16 + g) * 8 + tig * 2);
    a0l[1] = *(const uint32_t*)(xs + (w * 16 + g + 8) * 8 + tig * 2);
    a0l[2] = 0u;
    a0l[3] = 0u;

    // ================= layer 0 (mma) =================
    float acc[16][4];
    #pragma unroll
    for (int nt = 0; nt < 16; nt++)
        #pragma unroll
        for (int q = 0; q < 4; q++) acc[nt][q] = 0.f;
    #pragma unroll
    for (int ntp = 0; ntp < 8; ntp++) {
        uint4 bb = w0f[ntp * 32 + lane];
        mma_f16(acc[2 * ntp],     a0l, bb.x, bb.y);
        mma_f16(acc[2 * ntp + 1], a0l, bb.z, bb.w);
    }

    // ---- epilogue layer0: softplus (bias already folded in) -> frags ----
    uint32_t frag[8][4];
    #pragma unroll
    for (int kk = 0; kk < 8; kk++) {
        frag[kk][0] = f2h2(sp100p(acc[2 * kk][0]), sp100p(acc[2 * kk][1]));
        frag[kk][1] = f2h2(sp100p(acc[2 * kk][2]), sp100p(acc[2 * kk][3]));
        frag[kk][2] = f2h2(sp100p(acc[2 * kk + 1][0]), sp100p(acc[2 * kk + 1][1]));
        frag[kk][3] = f2h2(sp100p(acc[2 * kk + 1][2]), sp100p(acc[2 * kk + 1][3]));
    }

    // ================= layer 1 =================
    #pragma unroll
    for (int nt = 0; nt < 16; nt++)
        #pragma unroll
        for (int q = 0; q < 4; q++) acc[nt][q] = 0.f;
    #pragma unroll
    for (int kk = 0; kk < 8; kk++) {
        const uint4* wrow = wf + kk * 256 + lane;
        #pragma unroll
        for (int ntp = 0; ntp < 8; ntp++) {
            uint4 bb = wrow[ntp * 32];
            mma_f16(acc[2 * ntp],     frag[kk], bb.x, bb.y);
            mma_f16(acc[2 * ntp + 1], frag[kk], bb.z, bb.w);
        }
    }

    // ---- epilogue layer1: bias + softplus -> frags ----
    #pragma unroll
    for (int kk = 0; kk < 8; kk++) {
        int n0 = kk * 16 + tig * 2;
        int n1 = n0 + 8;
        frag[kk][0] = f2h2(sp100p(acc[2 * kk][0] + b1s[n0]), sp100p(acc[2 * kk][1] + b1s[n0 + 1]));
        frag[kk][1] = f2h2(sp100p(acc[2 * kk][2] + b1s[n0]), sp100p(acc[2 * kk][3] + b1s[n0 + 1]));
        frag[kk][2] = f2h2(sp100p(acc[2 * kk + 1][0] + b1s[n1]), sp100p(acc[2 * kk + 1][1] + b1s[n1 + 1]));
        frag[kk][3] = f2h2(sp100p(acc[2 * kk + 1][2] + b1s[n1]), sp100p(acc[2 * kk + 1][3] + b1s[n1 + 1]));
    }

    // ================= layer 2 =================
    #pragma unroll
    for (int nt = 0; nt < 16; nt++)
        #pragma unroll
        for (int q = 0; q < 4; q++) acc[nt][q] = 0.f;
    #pragma unroll
    for (int kk = 0; kk < 8; kk++) {
        const uint4* wrow = wf + 2048 + kk * 256 + lane;
        #pragma unroll
        for (int ntp = 0; ntp < 8; ntp++) {
            uint4 bb = wrow[ntp * 32];
            mma_f16(acc[2 * ntp],     frag[kk], bb.x, bb.y);
            mma_f16(acc[2 * ntp + 1], frag[kk], bb.z, bb.w);
        }
    }

    // ---- epilogue layer2 + layer3 dot + quad reduce ----
    {
        float dot0 = 0.f, dot1 = 0.f;
        #pragma unroll
        for (int nt = 0; nt < 16; nt++) {
            int n = nt * 8 + tig * 2;
            dot0 += sp100p(acc[nt][0] + b2s[n]) * w3s[n];
            dot0 += sp100p(acc[nt][1] + b2s[n + 1]) * w3s[n + 1];
            dot1 += sp100p(acc[nt][2] + b2s[n]) * w3s[n];
            dot1 += sp100p(acc[nt][3] + b2s[n + 1]) * w3s[n + 1];
        }
        dot0 += __shfl_xor_sync(0xffffffffu, dot0, 1);
        dot0 += __shfl_xor_sync(0xffffffffu, dot0, 2);
        dot1 += __shfl_xor_sync(0xffffffffu, dot1, 1);
        dot1 += __shfl_xor_sync(0xffffffffu, dot1, 2);
        if (tig == 0) {
            float bb = b3[j];
            int m0 = w * 16 + g;
            int va = v0 + m0;
            int vb = v0 + m0 + 8;
            if (va < NV) g_pred[j][va] = dot0 + bb;
            if (vb < NV) g_pred[j][vb] = dot1 + bb;
        }
    }
}

// ---------------------------------------------------------------------------
// Softmin blend over parts
// ---------------------------------------------------------------------------
__global__ void softmin_kernel(float* __restrict__ out) {
    int v = blockIdx.x * blockDim.x + threadIdx.x;
    if (v >= NV) return;
    float p[NJ];
    float mn = 3.0e38f;
    #pragma unroll
    for (int j = 0; j < NJ; j++) { p[j] = g_pred[j][v]; mn = fminf(mn, p[j]); }
    float se = 0.f, sd = 0.f;
    #pragma unroll
    for (int j = 0; j < NJ; j++) {
        float d = p[j] - mn;
        float e = expf(-200.0f * d);
        se += e;
        sd += d * e;
    }
    out[v] = sd / se + mn;
}

extern "C" void kernel_launch(void* const* d_in, const int* in_sizes, int n_in,
                              void* d_out, int out_size)
{
    const float* pts    = (const float*)d_in[0];
    const float* Bcond  = (const float*)d_in[1];
    const float* Btr    = (const float*)d_in[2];
    const float* Brot   = (const float*)d_in[3];
    const float* Bneigh = (const float*)d_in[4];
    const float* alpha  = (const float*)d_in[5];
    const float* beta   = (const float*)d_in[6];
    const float* cW0 = (const float*)d_in[7];
    const float* cb0 = (const float*)d_in[8];
    const float* cW1 = (const float*)d_in[9];
    const float* cb1 = (const float*)d_in[10];
    const float* cW2 = (const float*)d_in[11];
    const float* cb2 = (const float*)d_in[12];
    const float* W0  = (const float*)d_in[13];
    const float* b0  = (const float*)d_in[14];
    const float* W1  = (const float*)d_in[15];
    const float* b1  = (const float*)d_in[16];
    const float* W2  = (const float*)d_in[17];
    const float* b2  = (const float*)d_in[18];
    const float* W3  = (const float*)d_in[19];
    const float* b3  = (const float*)d_in[20];

    cudaFuncSetAttribute(setup_kernel, cudaFuncAttributeMaxDynamicSharedMemorySize, SMEM_SETUP);
    cudaFuncSetAttribute(main_kernel, cudaFuncAttributeMaxDynamicSharedMemorySize, SMEM_MAIN);

    setup_kernel<<<3 * NJ, 256, SMEM_SETUP>>>(W1, W2, Bcond, Bneigh, alpha, beta,
                                              cW0, cb0, cW1, cb1, cW2, cb2, W0, b0);

    dim3 grid((NV + MTILE - 1) / MTILE, NJ);
    main_kernel<<<grid, TPB, SMEM_MAIN>>>(pts, Btr, Brot, b1, b2, W3, b3);

    softmin_kernel<<<(NV + 255) / 256, 256>>>((float*)d_out);
}